// round 10
// baseline (speedup 1.0000x reference)
#include <cuda_runtime.h>
#include <math.h>

// QuantumPoolingLayer R10: pool unchanged (contiguous 256 KiB blocks, ~94% HBM).
// Sim: 4 threads/sample (amp-distributed over lanes), CNOT layers folded into
// butterfly masks (derived: layer2 gate q pairs x with x^V, V in {15,7,3,1},
// side bit = parity(x & R), R in {8,12,6,3}; measurement sign = bit w0 = t&2).

#define NQ 4

__device__ float2 g_part[64 * 32 * 512];   // [b][rg][m] -> (ch0, ch1) partials

struct c32 { float x, y; };
__device__ __forceinline__ c32 cadd(c32 a, c32 b){ return {a.x+b.x, a.y+b.y}; }
__device__ __forceinline__ c32 cmul(c32 a, c32 b){
    return { fmaf(a.x, b.x, -a.y*b.y), fmaf(a.x, b.y, a.y*b.x) };
}

// K1: grid (rg=32, b=64), 512 threads, 2 blocks/SM.
// Block streams rows [rg*2, rg*2+2), all j, all m: 256 KB CONTIGUOUS.
__global__ void __launch_bounds__(512, 2)
pool_kernel(const float* __restrict__ in)
{
    const int rg = blockIdx.x;           // 2-row group, 0..31
    const int b  = blockIdx.y;
    const int tid = threadIdx.x;
    const int ml  = tid & 127;           // m float4 lane
    const int p   = tid >> 7;            // 0..3

    const float* tb = in
        + ((size_t)(b * 64 + rg * 2) * 64) * 512
        + (size_t)p * 512 + (ml << 2);

    float4 acc0 = {0.f,0.f,0.f,0.f};     // colhalf 0 (j < 32)
    float4 acc1 = {0.f,0.f,0.f,0.f};     // colhalf 1 (j >= 32)

#pragma unroll
    for (int il = 0; il < 2; il++) {
        const float* rbase = tb + (size_t)il * 64 * 512;
        {
            float4 v[8];
#pragma unroll
            for (int k = 0; k < 8; k++)
                v[k] = __ldcs(reinterpret_cast<const float4*>(rbase + (size_t)k * 2048));
#pragma unroll
            for (int k = 0; k < 8; k++) {
                acc0.x += v[k].x; acc0.y += v[k].y; acc0.z += v[k].z; acc0.w += v[k].w;
            }
        }
        {
            float4 v[8];
#pragma unroll
            for (int k = 0; k < 8; k++)
                v[k] = __ldcs(reinterpret_cast<const float4*>(rbase + (size_t)(k + 8) * 2048));
#pragma unroll
            for (int k = 0; k < 8; k++) {
                acc1.x += v[k].x; acc1.y += v[k].y; acc1.z += v[k].z; acc1.w += v[k].w;
            }
        }
    }

    __shared__ float part[4][2][512];    // [p][ch][m], 16 KB
    reinterpret_cast<float4*>(part[p][0])[ml] = acc0;
    reinterpret_cast<float4*>(part[p][1])[ml] = acc1;
    __syncthreads();

    {
        float s0 = part[0][0][tid] + part[1][0][tid] + part[2][0][tid] + part[3][0][tid];
        float s1 = part[0][1][tid] + part[1][1][tid] + part[2][1][tid] + part[3][1][tid];
        g_part[(size_t)(b * 32 + rg) * 512 + tid] = make_float2(s0, s1);
    }
}

// Complex butterfly on distributed state: amp x = (t<<2)|l, partner x^V,
// side s(x) = parity(x & R). V,R compile-time.
template<int V, int R>
__device__ __forceinline__ void gate_c(c32 a[4], int t,
                                       c32 U00, c32 U01, c32 U10, c32 U11)
{
    const int vt = V >> 2, vl = V & 3;
    c32 pv[4];
#pragma unroll
    for (int l = 0; l < 4; l++) {
        c32 src = a[l ^ vl];
        if (vt) {
            src.x = __shfl_xor_sync(0xFFFFFFFFu, src.x, vt);
            src.y = __shfl_xor_sync(0xFFFFFFFFu, src.y, vt);
        }
        pv[l] = src;
    }
#pragma unroll
    for (int l = 0; l < 4; l++) {
        const int x = (t << 2) | l;
        const int s = __popc(x & R) & 1;
        c32 own = a[l], p = pv[l];
        c32 n0 = cadd(cmul(U00, own), cmul(U01, p));   // s == 0
        c32 n1 = cadd(cmul(U10, p), cmul(U11, own));   // s == 1
        a[l] = s ? n1 : n0;
    }
}

// Real RY butterfly (state real during embedding): V == R for layer-1 wires.
template<int V>
__device__ __forceinline__ void gate_ry(float r[4], int t, float sn, float cs)
{
    const int vt = V >> 2, vl = V & 3;
    float pv[4];
#pragma unroll
    for (int l = 0; l < 4; l++) {
        float src = r[l ^ vl];
        if (vt) src = __shfl_xor_sync(0xFFFFFFFFu, src, vt);
        pv[l] = src;
    }
#pragma unroll
    for (int l = 0; l < 4; l++) {
        const int x = (t << 2) | l;
        const int s = (x & V) ? 1 : 0;
        // s==0: cs*own - sn*pv ; s==1: cs*own + sn*pv
        r[l] = fmaf(s ? sn : -sn, pv[l], cs * r[l]);
    }
}

// K2: 4 threads/sample. Grid 512 x 256 (64 samples/block, widx == blockIdx).
__global__ void __launch_bounds__(256)
sim_kernel(const float* __restrict__ w, float* __restrict__ out)
{
    const int tid = threadIdx.x;
    const int t   = tid & 3;                      // amp prefix (w0,w1)
    const int n   = blockIdx.x * 64 + (tid >> 2); // sample
    const int b = n >> 9;
    const int m = n & 511;

    // --- scratch combine: lane t loads rg in [8t, 8t+8), then 4-lane reduce ---
    float quad[4] = {0.f, 0.f, 0.f, 0.f};
#pragma unroll
    for (int i = 0; i < 8; i++) {
        const int rg = t * 8 + i;
        float2 v = g_part[(size_t)(b * 32 + rg) * 512 + m];
        const int rh = rg >> 4;
        quad[rh * 2 + 0] += v.x;
        quad[rh * 2 + 1] += v.y;
    }

    // --- block-level gate table (widx == blockIdx for all warps) ---
    __shared__ float sc[8][3][2];   // [gate][comp][sin,cos]
    __shared__ float gt[8][4];      // [gate][A,B,C,D]
    const float* wp = w + (size_t)blockIdx.x * 24;
    if (tid < 24) {
        const int g = tid / 3, c = tid - g * 3;
        float phi = wp[g * 3 + 0], th = wp[g * 3 + 1], om = wp[g * 3 + 2];
        float arg = (c == 0) ? 0.5f * th
                  : (c == 1) ? 0.5f * (phi + om)
                             : 0.5f * (phi - om);
        float sn, cs; __sincosf(arg, &sn, &cs);
        sc[g][c][0] = sn; sc[g][c][1] = cs;
    }
    __syncthreads();
    if (tid < 8) {
        float stt = sc[tid][0][0], ctt = sc[tid][0][1];
        float sa  = sc[tid][1][0], ca  = sc[tid][1][1];
        float sb  = sc[tid][2][0], cb  = sc[tid][2][1];
        gt[tid][0] = ctt * ca;   // A
        gt[tid][1] = ctt * sa;   // B
        gt[tid][2] = stt * cb;   // C
        gt[tid][3] = stt * sb;   // D
    }

    // --- 4-lane quad reduce + tanh (while gate table settles) ---
#pragma unroll
    for (int q = 0; q < 4; q++) {
        quad[q] += __shfl_xor_sync(0xFFFFFFFFu, quad[q], 1);
        quad[q] += __shfl_xor_sync(0xFFFFFFFFu, quad[q], 2);
    }
    float sn0[4], cs0[4];
#pragma unroll
    for (int q = 0; q < 4; q++) {
        float x = tanhf(quad[q] * (1.0f / 1024.0f));
        __sincosf(x * 1.57079632679489662f, &sn0[q], &cs0[q]);
    }
    __syncthreads();   // gt ready

    // --- state: real RY embedding (wires 0..3, masks 8,4,2,1) ---
    float r[4] = { (t == 0) ? 1.f : 0.f, 0.f, 0.f, 0.f };
    gate_ry<8>(r, t, sn0[0], cs0[0]);
    gate_ry<4>(r, t, sn0[1], cs0[1]);
    gate_ry<2>(r, t, sn0[2], cs0[2]);
    gate_ry<1>(r, t, sn0[3], cs0[3]);

    c32 a[4];
#pragma unroll
    for (int l = 0; l < 4; l++) a[l] = { r[l], 0.f };

    // --- Rot gates; CNOT layers folded into masks ---
#pragma unroll
    for (int g = 0; g < 8; g++) {
        const float A = gt[g][0], B = gt[g][1], C = gt[g][2], D = gt[g][3];
        c32 U00 = {  A, -B };
        c32 U01 = { -C, -D };
        c32 U10 = {  C, -D };
        c32 U11 = {  A,  B };
        switch (g) {
            case 0: gate_c<8, 8 >(a, t, U00, U01, U10, U11); break;  // L1 q0
            case 1: gate_c<4, 4 >(a, t, U00, U01, U10, U11); break;  // L1 q1
            case 2: gate_c<2, 2 >(a, t, U00, U01, U10, U11); break;  // L1 q2
            case 3: gate_c<1, 1 >(a, t, U00, U01, U10, U11); break;  // L1 q3
            case 4: gate_c<15, 8>(a, t, U00, U01, U10, U11); break;  // L2 q0
            case 5: gate_c<7, 12>(a, t, U00, U01, U10, U11); break;  // L2 q1
            case 6: gate_c<3, 6 >(a, t, U00, U01, U10, U11); break;  // L2 q2
            case 7: gate_c<1, 3 >(a, t, U00, U01, U10, U11); break;  // L2 q3
        }
    }

    // --- <Z0>: sign = physical bit w0 = t&2 (second CNOT layer folded) ---
    float p = 0.f;
#pragma unroll
    for (int l = 0; l < 4; l++)
        p += fmaf(a[l].x, a[l].x, a[l].y * a[l].y);
    p = (t & 2) ? -p : p;
    p += __shfl_xor_sync(0xFFFFFFFFu, p, 1);
    p += __shfl_xor_sync(0xFFFFFFFFu, p, 2);
    if (t == 0) out[n] = p;
}

extern "C" void kernel_launch(void* const* d_in, const int* in_sizes, int n_in,
                              void* d_out, int out_size)
{
    const float* in = (const float*)d_in[0];
    const float* w  = (const float*)d_in[1];
    if (n_in >= 2 && in_sizes[0] < in_sizes[1]) {   // defensive: identify by size
        in = (const float*)d_in[1];
        w  = (const float*)d_in[0];
    }
    dim3 grid1(32, 64);
    pool_kernel<<<grid1, 512>>>(in);
    sim_kernel<<<512, 256>>>(w, (float*)d_out);
}